// round 10
// baseline (speedup 1.0000x reference)
#include <cuda_runtime.h>
#include <cuda_fp16.h>
#include <math.h>
#include <stdint.h>

// Histogram2D as GEMM on mma.sync: per 128-point chunk build f16 tiles
//   A[m][k] = wx weight of point k at x-bin m   (128x128, 256B rows, XOR swz)
//   B[n][k] = wy weight of point k at y-bin n
// accumulate D += A.B^T with m16n8k16 HMMA into per-warp fp32 registers.
// Each point owns one k-column -> race-free STS.16, zero atomics.
// R10: occupancy 2 (296 CTAs), double-buffered coalesced point staging.

#define NB      128
#define W       9
#define LROWS   9728         // LUT: g = tpos - s0 + 5 in [0,19), 512 steps/bin
#define THREADS 256
#define CTAS    296          // 2 CTAs/SM * 148 SMs
#define RBLK    64
#define TILE    32768        // one 128x128 f16 tile (256B per bin-row)
#define PTSF    768          // floats per chunk of 128 points (x[:,0..5])
#define SMEMSZ  (2*TILE + 2*PTSF*4)

__device__ __align__(16) uint32_t g_lut[LROWS * 8];  // 16 halves/row (9 used)
__device__ float g_part[CTAS * NB * NB];
__device__ float g_hist[NB * NB];
__device__ float g_bsum[RBLK];

// ---------------- helpers ----------------
__device__ __forceinline__ uint32_t smem_u32(const void* p) {
    uint32_t a;
    asm("{ .reg .u64 t; cvta.to.shared.u64 t, %1; cvt.u32.u64 %0, t; }"
        : "=r"(a) : "l"(p));
    return a;
}
__device__ __forceinline__ void ldm_x4(uint32_t* r, uint32_t addr) {
    asm volatile("ldmatrix.sync.aligned.m8n8.x4.shared.b16 {%0,%1,%2,%3}, [%4];"
        : "=r"(r[0]), "=r"(r[1]), "=r"(r[2]), "=r"(r[3]) : "r"(addr));
}
__device__ __forceinline__ void mma16816(float* c, const uint32_t* a,
                                         const uint32_t* b) {
    asm volatile("mma.sync.aligned.m16n8k16.row.col.f32.f16.f16.f32 "
        "{%0,%1,%2,%3}, {%4,%5,%6,%7}, {%8,%9}, {%0,%1,%2,%3};"
        : "+f"(c[0]), "+f"(c[1]), "+f"(c[2]), "+f"(c[3])
        : "r"(a[0]), "r"(a[1]), "r"(a[2]), "r"(a[3]), "r"(b[0]), "r"(b[1]));
}

// write 9 halves (or zeros) into column k of a tile.
// byte(m,k) = m*256 + ((k>>3) ^ (m&7))*16 + (k&7)*2  (swizzle for ldmatrix)
__device__ __forceinline__ void put9(char* tile, int k, int s0,
                                     const uint32_t* r) {
    const uint32_t kc = (uint32_t)k >> 3;
    const uint32_t kw = ((uint32_t)k & 7) << 1;
#pragma unroll
    for (int j = 0; j < W; j++) {
        uint32_t m = (uint32_t)(s0 + j);
        uint32_t b = (m << 8) + (((kc ^ (m & 7)) << 4) | kw);
        uint16_t v = r ? (uint16_t)(r[j >> 1] >> ((j & 1) << 4)) : (uint16_t)0;
        *(uint16_t*)(tile + b) = v;
    }
}

// ---------------- kernels ----------------
__global__ void lut_kernel() {
    int i = blockIdx.x * blockDim.x + threadIdx.x;
    if (i >= LROWS) return;
    const float c = 0.7071067811865475f;
    float g = ((float)i + 0.5f) / 512.0f - 5.0f;
    uint32_t out[8] = {0, 0, 0, 0, 0, 0, 0, 0};
    float prev = erff((0.0f - g) * c);
#pragma unroll
    for (int j = 0; j < W; j++) {
        float nx = erff(((float)(j + 1) - g) * c);
        uint32_t h = (uint32_t)__half_as_ushort(__float2half_rn(0.5f * (nx - prev)));
        out[j >> 1] |= h << ((j & 1) << 4);
        prev = nx;
    }
    uint4* dst = (uint4*)&g_lut[i * 8];
    dst[0] = make_uint4(out[0], out[1], out[2], out[3]);
    dst[1] = make_uint4(out[4], out[5], out[6], out[7]);
}

__global__ __launch_bounds__(THREADS, 2)
void hist_kernel(const float* __restrict__ x, const float* __restrict__ ex,
                 int n, int nch)
{
    extern __shared__ char sm[];                 // [A 32K][B 32K][pts 2x3K]
    const uint32_t smb = smem_u32(sm);
    float* pts = (float*)(sm + 2 * TILE);        // [2][PTSF]
    const int tid  = threadIdx.x;
    const int lane = tid & 31;
    const int wrp  = tid >> 5;
    const int t    = tid & 127;                  // point slot within chunk
    const int mat  = tid >> 7;                   // 0: A (x), 1: B (y)
    const int cta  = blockIdx.x;
    const int nf4  = (n * 6) >> 2;               // float4 count in x

    for (int i = tid; i < (2 * TILE) / 16; i += THREADS)
        ((uint4*)sm)[i] = make_uint4(0, 0, 0, 0);

    const float lo     = __ldg(&ex[0]);
    const float inv_dx = 1.0f / (__ldg(&ex[1]) - lo);

    // warp-tile: 32 rows (m) x 64 cols (n)
    const int m_base = (wrp & 3) * 32;
    const int n_base = (wrp >> 2) * 64;
    const int lt = lane >> 3, l7 = lane & 7;
    const int a_hi = lt >> 1;
    const int a_m0 = m_base + (lt & 1) * 8 + l7;
    const int b_hi = lt & 1;
    const int b_n0 = n_base + (lt >> 1) * 8 + l7;

    float acc[2][8][4];
#pragma unroll
    for (int i = 0; i < 2; i++)
#pragma unroll
        for (int j = 0; j < 8; j++)
#pragma unroll
            for (int q = 0; q < 4; q++) acc[i][j][q] = 0.0f;

    char* mytile = sm + mat * TILE;
    int prev = 0;

    // stage chunk 0 points (coalesced float4)
    if (tid < PTSF / 4) {
        int f4 = cta * (PTSF / 4) + tid;
        if (f4 < nf4) ((float4*)pts)[tid] = ((const float4*)x)[f4];
    }
    __syncthreads();

    for (int i = 0; i < nch; i++) {
        const int b = i & 1;
        const float* pb = pts + b * PTSF;

        // ---- fill: clear previous entries, write this chunk's point column
        put9(mytile, t, prev, (const uint32_t*)0);
        int p = (cta + i * CTAS) * 128 + t;
        if (p < n) {
            float coord = pb[t * 6 + mat];
            float tp = (coord - lo) * inv_dx;
            int s0 = (int)floorf(tp) - 4;
            s0 = min(max(s0, 0), NB - W);
            int li = (int)((tp - (float)s0 + 5.0f) * 512.0f);
            li = min(max(li, 0), LROWS - 1);
            uint32_t r[6];
            const uint4 ra = *(const uint4*)&g_lut[li * 8];
            const uint2 rb = *(const uint2*)&g_lut[li * 8 + 4];
            r[0] = ra.x; r[1] = ra.y; r[2] = ra.z; r[3] = ra.w;
            r[4] = rb.x; r[5] = rb.y;
            put9(mytile, t, s0, r);
            prev = s0;
        }

        // ---- stage next chunk's points (overlaps the MMA phase below)
        if (i + 1 < nch && tid < PTSF / 4) {
            int f4 = (cta + (i + 1) * CTAS) * (PTSF / 4) + tid;
            if (f4 < nf4)
                ((float4*)(pts + (1 - b) * PTSF))[tid] = ((const float4*)x)[f4];
        }
        __syncthreads();

        // ---- MMA over this chunk's K=128
#pragma unroll
        for (int ks = 0; ks < 8; ks++) {
            uint32_t af0[4], af1[4];
            const uint32_t swa = (uint32_t)(((ks * 2 + a_hi) ^ l7) << 4);
            ldm_x4(af0, smb + (uint32_t)a_m0 * 256 + swa);
            ldm_x4(af1, smb + (uint32_t)(a_m0 + 16) * 256 + swa);
            const uint32_t swb = (uint32_t)(((ks * 2 + b_hi) ^ l7) << 4);
#pragma unroll
            for (int nt2 = 0; nt2 < 4; nt2++) {
                uint32_t bf[4];
                ldm_x4(bf, smb + TILE + (uint32_t)(b_n0 + nt2 * 16) * 256 + swb);
                mma16816(acc[0][nt2 * 2 + 0], af0, bf);
                mma16816(acc[0][nt2 * 2 + 1], af0, bf + 2);
                mma16816(acc[1][nt2 * 2 + 0], af1, bf);
                mma16816(acc[1][nt2 * 2 + 1], af1, bf + 2);
            }
        }
        __syncthreads();
    }

    // ---- readout: per-warp D tile -> per-CTA partial
    float* dst = g_part + cta * (NB * NB);
    const int col0 = (lane & 3) * 2;
#pragma unroll
    for (int mt = 0; mt < 2; mt++) {
        int row = m_base + mt * 16 + (lane >> 2);
#pragma unroll
        for (int nt = 0; nt < 8; nt++) {
            int col = n_base + nt * 8 + col0;
            *(float2*)&dst[row * NB + col] =
                make_float2(acc[mt][nt][0], acc[mt][nt][1]);
            *(float2*)&dst[(row + 8) * NB + col] =
                make_float2(acc[mt][nt][2], acc[mt][nt][3]);
        }
    }
}

__global__ void reduce_kernel()
{
    __shared__ float red[THREADS];
    int bin = blockIdx.x * THREADS + threadIdx.x;
    float s = 0.0f;
#pragma unroll 4
    for (int cta = 0; cta < CTAS; cta++)
        s += g_part[cta * (NB * NB) + bin];
    g_hist[bin] = s;

    red[threadIdx.x] = s;
    __syncthreads();
    for (int off = THREADS / 2; off > 0; off >>= 1) {
        if (threadIdx.x < off) red[threadIdx.x] += red[threadIdx.x + off];
        __syncthreads();
    }
    if (threadIdx.x == 0) g_bsum[blockIdx.x] = red[0];
}

__global__ void norm_kernel(const float* __restrict__ ex,
                            float* __restrict__ out)
{
    float tot = 0.0f;
#pragma unroll
    for (int i = 0; i < RBLK; i++) tot += g_bsum[i];
    float dx = ex[1] - ex[0];
    float sc = 1.0f / (tot * dx * dx);
    int b = blockIdx.x * THREADS + threadIdx.x;
    out[b] = g_hist[b] * sc;
}

extern "C" void kernel_launch(void* const* d_in, const int* in_sizes, int n_in,
                              void* d_out, int out_size)
{
    const float* x  = (const float*)d_in[0];
    const float* ex = (const float*)d_in[1];
    float* out = (float*)d_out;
    int n = in_sizes[0] / 6;
    int chunks = (n + 127) / 128;
    int nch = (chunks + CTAS - 1) / CTAS;
    if (nch < 1) nch = 1;

    cudaFuncSetAttribute(hist_kernel,
                         cudaFuncAttributeMaxDynamicSharedMemorySize, SMEMSZ);

    lut_kernel<<<(LROWS + 255) / 256, 256>>>();
    hist_kernel<<<CTAS, THREADS, SMEMSZ>>>(x, ex, n, nch);
    reduce_kernel<<<RBLK, THREADS>>>();
    norm_kernel<<<RBLK, THREADS>>>(ex, out);
}